// round 14
// baseline (speedup 1.0000x reference)
#include <cuda_runtime.h>
#include <cuda_bf16.h>
#include <math.h>
#include <cstdint>

#define NROW 12288
#define BSZ  4096
#define KPAD 8192

// ---------------- scratch (device globals; no allocations) ----------------
__device__ __nv_bfloat16 g_ah[(size_t)NROW * KPAD];  // conv output hi (permuted K)
__device__ __nv_bfloat16 g_al[(size_t)NROW * KPAD];  // conv output lo
__device__ __nv_bfloat16 g_fwh[256 * KPAD];          // fc_w1 hi (same permutation)
__device__ __nv_bfloat16 g_fwl[256 * KPAD];          // fc_w1 lo
__device__ __nv_bfloat16 g_qwh[4 * 256 * 256];       // q1_w1,q2_w1,q1_w2,q2_w2 hi
__device__ __nv_bfloat16 g_qwl[4 * 256 * 256];       // lo
__device__ __nv_bfloat16 g_kvh[3 * 384 * 128];       // per-agent [Wk;Wv;Wq_g] hi
__device__ __nv_bfloat16 g_kvl[3 * 384 * 128];       // lo
__device__ __nv_bfloat16 g_cw2h[32 * 104];           // conv w2 pre-split (smem layout)
__device__ __nv_bfloat16 g_cw2l[32 * 104];
__device__ float g_act1[(size_t)NROW * 256];         // fc1 accumulator (atomic)
__device__ float g_inps[NROW * 60];
__device__ float g_stats[128];
__device__ __nv_bfloat16 g_embh[NROW * 256];
__device__ __nv_bfloat16 g_embl[NROW * 256];
__device__ __nv_bfloat16 g_mh[(size_t)NROW * 512];
__device__ __nv_bfloat16 g_ml[(size_t)NROW * 512];
__device__ float g_keys[NROW * 128];
__device__ float g_vals[NROW * 128];
__device__ float g_q[NROW * 128];

// ====================== helpers ======================
__device__ __forceinline__ uint32_t smem_u32(const void* p) {
    uint32_t a;
    asm("{ .reg .u64 t; cvta.to.shared.u64 t, %1; cvt.u32.u64 %0, t; }"
        : "=r"(a) : "l"(p));
    return a;
}
__device__ __forceinline__ void bsplit(float v, __nv_bfloat16& h, __nv_bfloat16& l) {
    h = __float2bfloat16(v);
    l = __float2bfloat16(v - __bfloat162float(h));
}
#define CPA16(s, g) \
    asm volatile("cp.async.cg.shared.global [%0], [%1], 16;" :: "r"(s), "l"(g))
#define CPC() asm volatile("cp.async.commit_group;" ::: "memory")
#define LDSM4(r0, r1, r2, r3, a) \
    asm volatile("ldmatrix.sync.aligned.m8n8.x4.shared.b16 {%0,%1,%2,%3}, [%4];" \
                 : "=r"(r0), "=r"(r1), "=r"(r2), "=r"(r3) : "r"(a))
#define MMA16816(d, a, b) \
    asm volatile("mma.sync.aligned.m16n8k16.row.col.f32.bf16.bf16.f32 " \
                 "{%0,%1,%2,%3},{%4,%5,%6,%7},{%8,%9},{%0,%1,%2,%3};" \
                 : "+f"((d)[0]), "+f"((d)[1]), "+f"((d)[2]), "+f"((d)[3]) \
                 : "r"((a)[0]), "r"((a)[1]), "r"((a)[2]), "r"((a)[3]), \
                   "r"((b)[0]), "r"((b)[1]))

// ================= fc1: bf16x3 GEMM, BM128/BN128/BK32, 3-stage, K-split =========
#define FSMEM (3 * 32768)
__global__ void __launch_bounds__(256, 2) fc1_gemm()
{
    extern __shared__ char smem[];
    const uint32_t sb = smem_u32(smem);

    const int t = threadIdx.x, lane = t & 31, wid = t >> 5;
    const int bn = blockIdx.x, bm = blockIdx.y, z = blockIdx.z;
    const int kt0 = (z == 0) ? 0 : (z == 1) ? 86 : 171;
    const int T   = (z == 0) ? 86 : 85;
    const int row0 = bm * 128, col0 = bn * 128;

    const int fr = t >> 1;
    const int c0 = (t & 1) * 2;
    const __nv_bfloat16* gAh = g_ah + (size_t)(row0 + fr) * KPAD + kt0 * 32;
    const __nv_bfloat16* gAl = g_al + (size_t)(row0 + fr) * KPAD + kt0 * 32;
    const __nv_bfloat16* gBh = g_fwh + (size_t)(col0 + fr) * KPAD + kt0 * 32;
    const __nv_bfloat16* gBl = g_fwl + (size_t)(col0 + fr) * KPAD + kt0 * 32;
    const int fsw = (fr >> 1) & 3;

    const int mw = wid & 1, nw = wid >> 1;

    float acc[4][4][4];
    #pragma unroll
    for (int a = 0; a < 4; a++)
        #pragma unroll
        for (int b = 0; b < 4; b++)
            #pragma unroll
            for (int c = 0; c < 4; c++) acc[a][b][c] = 0.f;

    auto fill = [&](int tt, int s) {
        uint32_t base = sb + s * 32768;
        const __nv_bfloat16* pAh = gAh + (size_t)tt * 32;
        const __nv_bfloat16* pAl = gAl + (size_t)tt * 32;
        const __nv_bfloat16* pBh = gBh + (size_t)tt * 32;
        const __nv_bfloat16* pBl = gBl + (size_t)tt * 32;
        #pragma unroll
        for (int j = 0; j < 2; j++) {
            int c = c0 + j;
            uint32_t off = fr * 64 + ((c ^ fsw) << 4);
            CPA16(base + off,         pAh + c * 8);
            CPA16(base + 8192 + off,  pAl + c * 8);
            CPA16(base + 16384 + off, pBh + c * 8);
            CPA16(base + 24576 + off, pBl + c * 8);
        }
    };

    fill(0, 0); CPC();
    fill(1, 1); CPC();

    for (int tt = 0; tt < T; tt++) {
        asm volatile("cp.async.wait_group 1;" ::: "memory");
        __syncthreads();

        const uint32_t stu = sb + (tt % 3) * 32768;
        #pragma unroll
        for (int ks = 0; ks < 2; ks++) {
            uint32_t bhf[2][4], blf[2][4];
            #pragma unroll
            for (int nt = 0; nt < 2; nt++) {
                int nr = nw * 32 + nt * 16 + (lane & 7) + ((lane >> 4) << 3);
                int cs = (ks * 2 + ((lane >> 3) & 1)) ^ ((nr >> 1) & 3);
                uint32_t ba = stu + 16384 + nr * 64 + cs * 16;
                LDSM4(bhf[nt][0], bhf[nt][1], bhf[nt][2], bhf[nt][3], ba);
                LDSM4(blf[nt][0], blf[nt][1], blf[nt][2], blf[nt][3], ba + 8192);
            }
            #pragma unroll
            for (int mi = 0; mi < 4; mi++) {
                int r = mw * 64 + mi * 16 + (lane & 15);
                int cs = (ks * 2 + (lane >> 4)) ^ ((r >> 1) & 3);
                uint32_t aa = stu + r * 64 + cs * 16;
                uint32_t ah[4], al[4];
                LDSM4(ah[0], ah[1], ah[2], ah[3], aa);
                LDSM4(al[0], al[1], al[2], al[3], aa + 8192);
                #pragma unroll
                for (int nj = 0; nj < 4; nj++) {
                    int nt = nj >> 1, hf = (nj & 1) * 2;
                    MMA16816(acc[mi][nj], ah, &bhf[nt][hf]);
                    MMA16816(acc[mi][nj], ah, &blf[nt][hf]);
                    MMA16816(acc[mi][nj], al, &bhf[nt][hf]);
                }
            }
        }

        if (tt + 2 < T) fill(tt + 2, (tt + 2) % 3);
        CPC();
    }

    // epilogue: atomic accumulate into g_act1 (pre-zeroed)
    #pragma unroll
    for (int mi = 0; mi < 4; mi++) {
        #pragma unroll
        for (int nj = 0; nj < 4; nj++) {
            int col = col0 + nw * 32 + nj * 8 + (lane & 3) * 2;
            #pragma unroll
            for (int h = 0; h < 2; h++) {
                int row = row0 + mw * 64 + mi * 16 + (lane >> 2) + h * 8;
                float* p = g_act1 + (size_t)row * 256 + col;
                atomicAdd(p,     acc[mi][nj][h * 2]);
                atomicAdd(p + 1, acc[mi][nj][h * 2 + 1]);
            }
        }
    }
}

// ============ MLP GEMM: BM64/BN128/BK32, 3-stage, warp tile 32x32, bf16x3 ========
#define GSMEM1 (3 * 24576)
#define GSMEM2 (3 * 24576 + 1024)
template <int LAYER>
__global__ void __launch_bounds__(256, 2) mlp_gemm(
    const float* __restrict__ biasA, const float* __restrict__ biasB,
    const float* __restrict__ w3a, const float* __restrict__ w3b,
    float* __restrict__ out)
{
    const int z = (LAYER == 2) ? blockIdx.z : 0;
    const __nv_bfloat16* Ah = (LAYER == 1) ? g_embh : g_mh + z * 256;
    const __nv_bfloat16* Al = (LAYER == 1) ? g_embl : g_ml + z * 256;
    const int AS = (LAYER == 1) ? 256 : 512;
    const __nv_bfloat16* Bh = (LAYER == 1) ? g_qwh : g_qwh + (2 + z) * 65536;
    const __nv_bfloat16* Bl = (LAYER == 1) ? g_qwl : g_qwl + (2 + z) * 65536;

    extern __shared__ char smem[];
    const uint32_t sb = smem_u32(smem);
    float* w3s = (float*)(smem + 73728);

    const int t = threadIdx.x, lane = t & 31, wid = t >> 5;
    const int row0 = blockIdx.y * 64, col0 = blockIdx.x * 128;

    if (LAYER == 2) {
        if (t < 256) w3s[t] = (z ? w3b : w3a)[t];
    }

    const int ar = t >> 2, ac = t & 3;
    const int br = t >> 1, bc0 = (t & 1) * 2;
    const __nv_bfloat16* gAh = Ah + (size_t)(row0 + ar) * AS + ac * 8;
    const __nv_bfloat16* gAl = Al + (size_t)(row0 + ar) * AS + ac * 8;
    const __nv_bfloat16* gBh = Bh + (size_t)(col0 + br) * 256;
    const __nv_bfloat16* gBl = Bl + (size_t)(col0 + br) * 256;
    const uint32_t aoff = ar * 64 + ((ac ^ ((ar >> 1) & 3)) << 4);
    const int bsw = (br >> 1) & 3;

    const int mw = wid & 1, nw = wid >> 1;

    float acc[2][4][4];
    #pragma unroll
    for (int a = 0; a < 2; a++)
        #pragma unroll
        for (int b = 0; b < 4; b++)
            #pragma unroll
            for (int c = 0; c < 4; c++) acc[a][b][c] = 0.f;

    auto fill = [&](int tt, int s) {
        uint32_t base = sb + s * 24576;
        CPA16(base + aoff,        gAh + tt * 32);
        CPA16(base + 4096 + aoff, gAl + tt * 32);
        #pragma unroll
        for (int j = 0; j < 2; j++) {
            int c = bc0 + j;
            uint32_t boff = br * 64 + ((c ^ bsw) << 4);
            CPA16(base + 8192 + boff,  gBh + tt * 32 + c * 8);
            CPA16(base + 16384 + boff, gBl + tt * 32 + c * 8);
        }
    };

    fill(0, 0); CPC();
    fill(1, 1); CPC();

    const int T = 8;
    for (int tt = 0; tt < T; tt++) {
        asm volatile("cp.async.wait_group 1;" ::: "memory");
        __syncthreads();

        const uint32_t stu = sb + (tt % 3) * 24576;
        #pragma unroll
        for (int ks = 0; ks < 2; ks++) {
            uint32_t bhf[2][4], blf[2][4];
            #pragma unroll
            for (int nt = 0; nt < 2; nt++) {
                int nr = nw * 32 + nt * 16 + (lane & 7) + ((lane >> 4) << 3);
                int cs = (ks * 2 + ((lane >> 3) & 1)) ^ ((nr >> 1) & 3);
                uint32_t ba = stu + 8192 + nr * 64 + cs * 16;
                LDSM4(bhf[nt][0], bhf[nt][1], bhf[nt][2], bhf[nt][3], ba);
                LDSM4(blf[nt][0], blf[nt][1], blf[nt][2], blf[nt][3], ba + 8192);
            }
            #pragma unroll
            for (int mi = 0; mi < 2; mi++) {
                int r = mw * 32 + mi * 16 + (lane & 15);
                int cs = (ks * 2 + (lane >> 4)) ^ ((r >> 1) & 3);
                uint32_t aa = stu + r * 64 + cs * 16;
                uint32_t ah[4], al[4];
                LDSM4(ah[0], ah[1], ah[2], ah[3], aa);
                LDSM4(al[0], al[1], al[2], al[3], aa + 4096);
                #pragma unroll
                for (int nj = 0; nj < 4; nj++) {
                    int nt = nj >> 1, hf = (nj & 1) * 2;
                    MMA16816(acc[mi][nj], ah, &bhf[nt][hf]);
                    MMA16816(acc[mi][nj], ah, &blf[nt][hf]);
                    MMA16816(acc[mi][nj], al, &bhf[nt][hf]);
                }
            }
        }

        if (tt + 2 < T) fill(tt + 2, (tt + 2) % 3);
        CPC();
    }

    if (LAYER == 1) {
        #pragma unroll
        for (int mi = 0; mi < 2; mi++) {
            #pragma unroll
            for (int nj = 0; nj < 4; nj++) {
                int ocl = col0 + nw * 32 + nj * 8 + (lane & 3) * 2;
                float b0 = (ocl < 256) ? biasA[ocl] : biasB[ocl - 256];
                float b1 = (ocl + 1 < 256) ? biasA[ocl + 1] : biasB[ocl + 1 - 256];
                #pragma unroll
                for (int h = 0; h < 2; h++) {
                    int row = row0 + mw * 32 + mi * 16 + (lane >> 2) + h * 8;
                    float v0 = fmaxf(acc[mi][nj][h * 2 + 0] + b0, 0.f);
                    float v1 = fmaxf(acc[mi][nj][h * 2 + 1] + b1, 0.f);
                    size_t idx = (size_t)row * 512 + ocl;
                    __nv_bfloat16 h0, l0, h1, l1;
                    bsplit(v0, h0, l0);
                    bsplit(v1, h1, l1);
                    *(__nv_bfloat162*)(g_mh + idx) = __halves2bfloat162(h0, h1);
                    *(__nv_bfloat162*)(g_ml + idx) = __halves2bfloat162(l0, l1);
                }
            }
        }
    } else {
        const float* bb = z ? biasB : biasA;
        #pragma unroll
        for (int mi = 0; mi < 2; mi++) {
            #pragma unroll
            for (int h = 0; h < 2; h++) {
                int row = row0 + mw * 32 + mi * 16 + (lane >> 2) + h * 8;
                float s = 0.f;
                #pragma unroll
                for (int nj = 0; nj < 4; nj++) {
                    int ocl = col0 + nw * 32 + nj * 8 + (lane & 3) * 2;
                    float v0 = fmaxf(acc[mi][nj][h * 2 + 0] + bb[ocl], 0.f);
                    float v1 = fmaxf(acc[mi][nj][h * 2 + 1] + bb[ocl + 1], 0.f);
                    s += v0 * w3s[ocl] + v1 * w3s[ocl + 1];
                }
                s += __shfl_xor_sync(0xffffffffu, s, 1);
                s += __shfl_xor_sync(0xffffffffu, s, 2);
                if ((lane & 3) == 0) atomicAdd(&out[z * NROW + row], s);
            }
        }
    }
}

// ========= kvq_gemm: keys/vals/q via bf16x3, BM64/BN128/BK32, K=128 =========
__global__ void __launch_bounds__(256, 2) kvq_gemm(const float* __restrict__ bv)
{
    const int m = blockIdx.x;
    const int g = blockIdx.z;
    const int row0 = g * 4096 + blockIdx.y * 64;
    const int col0 = m * 128;

    extern __shared__ char smem[];
    const uint32_t sb = smem_u32(smem);

    const int t = threadIdx.x, lane = t & 31, wid = t >> 5;

    const int ar = t >> 2, ac = t & 3;
    const int br = t >> 1, bc0 = (t & 1) * 2;
    const __nv_bfloat16* gAh = g_embh + (size_t)(row0 + ar) * 256 + ac * 8;
    const __nv_bfloat16* gAl = g_embl + (size_t)(row0 + ar) * 256 + ac * 8;
    const __nv_bfloat16* gBh = g_kvh + (size_t)g * 49152 + (size_t)(col0 + br) * 128;
    const __nv_bfloat16* gBl = g_kvl + (size_t)g * 49152 + (size_t)(col0 + br) * 128;
    const uint32_t aoff = ar * 64 + ((ac ^ ((ar >> 1) & 3)) << 4);
    const int bsw = (br >> 1) & 3;

    const int mw = wid & 1, nw = wid >> 1;

    float acc[2][4][4];
    #pragma unroll
    for (int a = 0; a < 2; a++)
        #pragma unroll
        for (int b = 0; b < 4; b++)
            #pragma unroll
            for (int c = 0; c < 4; c++) acc[a][b][c] = 0.f;

    auto fill = [&](int tt, int s) {
        uint32_t base = sb + s * 24576;
        CPA16(base + aoff,        gAh + tt * 32);
        CPA16(base + 4096 + aoff, gAl + tt * 32);
        #pragma unroll
        for (int j = 0; j < 2; j++) {
            int c = bc0 + j;
            uint32_t boff = br * 64 + ((c ^ bsw) << 4);
            CPA16(base + 8192 + boff,  gBh + tt * 32 + c * 8);
            CPA16(base + 16384 + boff, gBl + tt * 32 + c * 8);
        }
    };

    fill(0, 0); CPC();
    fill(1, 1); CPC();

    const int T = 4;
    for (int tt = 0; tt < T; tt++) {
        if (tt == T - 1)
            asm volatile("cp.async.wait_group 0;" ::: "memory");
        else
            asm volatile("cp.async.wait_group 1;" ::: "memory");
        __syncthreads();

        const uint32_t stu = sb + (tt % 3) * 24576;
        #pragma unroll
        for (int ks = 0; ks < 2; ks++) {
            uint32_t bhf[2][4], blf[2][4];
            #pragma unroll
            for (int nt = 0; nt < 2; nt++) {
                int nr = nw * 32 + nt * 16 + (lane & 7) + ((lane >> 4) << 3);
                int cs = (ks * 2 + ((lane >> 3) & 1)) ^ ((nr >> 1) & 3);
                uint32_t ba = stu + 8192 + nr * 64 + cs * 16;
                LDSM4(bhf[nt][0], bhf[nt][1], bhf[nt][2], bhf[nt][3], ba);
                LDSM4(blf[nt][0], blf[nt][1], blf[nt][2], blf[nt][3], ba + 8192);
            }
            #pragma unroll
            for (int mi = 0; mi < 2; mi++) {
                int r = mw * 32 + mi * 16 + (lane & 15);
                int cs = (ks * 2 + (lane >> 4)) ^ ((r >> 1) & 3);
                uint32_t aa = stu + r * 64 + cs * 16;
                uint32_t ah[4], al[4];
                LDSM4(ah[0], ah[1], ah[2], ah[3], aa);
                LDSM4(al[0], al[1], al[2], al[3], aa + 4096);
                #pragma unroll
                for (int nj = 0; nj < 4; nj++) {
                    int nt = nj >> 1, hf = (nj & 1) * 2;
                    MMA16816(acc[mi][nj], ah, &bhf[nt][hf]);
                    MMA16816(acc[mi][nj], ah, &blf[nt][hf]);
                    MMA16816(acc[mi][nj], al, &bhf[nt][hf]);
                }
            }
        }

        if (tt + 2 < T) fill(tt + 2, (tt + 2) % 3);
        CPC();
    }

    float* Out = (m == 0) ? g_keys : (m == 1) ? g_vals : g_q;
    #pragma unroll
    for (int mi = 0; mi < 2; mi++) {
        #pragma unroll
        for (int nj = 0; nj < 4; nj++) {
            int col = nw * 32 + nj * 8 + (lane & 3) * 2;
            float b0 = 0.f, b1 = 0.f;
            if (m == 1) { b0 = bv[col]; b1 = bv[col + 1]; }
            #pragma unroll
            for (int h = 0; h < 2; h++) {
                int row = row0 + mw * 32 + mi * 16 + (lane >> 2) + h * 8;
                float v0 = acc[mi][nj][h * 2 + 0] + b0;
                float v1 = acc[mi][nj][h * 2 + 1] + b1;
                if (m == 1) {
                    v0 = (v0 >= 0.f) ? v0 : 0.01f * v0;
                    v1 = (v1 >= 0.f) ? v1 : 0.01f * v1;
                }
                *(float2*)(Out + (size_t)row * 128 + col) = make_float2(v0, v1);
            }
        }
    }
}

// ---------------- combined weight prep / init kernel ----------------
__global__ void wsplit_all(
    const float* __restrict__ fw,
    const float* __restrict__ qa, const float* __restrict__ qb,
    const float* __restrict__ qc, const float* __restrict__ qd,
    const float* __restrict__ cw2,
    const float* __restrict__ Wk, const float* __restrict__ Wv,
    const float* __restrict__ Wq,
    const float* __restrict__ b3a, const float* __restrict__ b3b,
    float* __restrict__ out)
{
    const int bx = blockIdx.x, t = threadIdx.x;
    if (bx < 8192) {
        int i = bx * 256 + t;
        int r  = i >> 13;
        int kp = i & (KPAD - 1);
        int wq  = kp >> 10;
        int rem = kp & 1023;
        int mi = rem >> 9;
        int c  = (rem >> 8) & 1;
        int l  = (rem >> 3) & 31;
        int e  = rem & 7;
        int idx = e & 3;
        int nj  = c * 2 + (e >> 2);
        int oc  = mi * 16 + (l >> 2) + (idx >> 1) * 8;
        int pos = wq * 32 + nj * 8 + (l & 3) * 2 + (e & 1);
        float v = (pos < 250) ? fw[r * 8000 + oc * 250 + pos] : 0.f;
        __nv_bfloat16 hh, ll;
        bsplit(v, hh, ll);
        g_fwh[i] = hh;
        g_fwl[i] = ll;
    } else if (bx < 9216) {
        int i = (bx - 8192) * 256 + t;
        int which = i >> 16, j = i & 65535;
        const float* src = (which == 0) ? qa : (which == 1) ? qb : (which == 2) ? qc : qd;
        __nv_bfloat16 hh, ll;
        bsplit(src[j], hh, ll);
        g_qwh[i] = hh;
        g_qwl[i] = ll;
    } else if (bx < 9792) {
        int j = (bx - 9216) * 256 + t;
        int g = j / 49152, rem = j % 49152;
        int rowj = rem >> 7, k = rem & 127;
        float v = (rowj < 128) ? Wk[rowj * 128 + k]
                : (rowj < 256) ? Wv[(rowj - 128) * 128 + k]
                : Wq[g * 16384 + (rowj - 256) * 128 + k];
        __nv_bfloat16 hh, ll;
        bsplit(v, hh, ll);
        g_kvh[j] = hh;
        g_kvl[j] = ll;
    } else if (bx < 9804) {
        int idx = (bx - 9792) * 256 + t;
        if (idx < 3072) {
            int oc = idx / 96, rem = idx % 96;
            int ic = rem / 3, tap = rem % 3;
            __nv_bfloat16 hh, ll;
            bsplit(cw2[idx], hh, ll);
            int o = oc * 104 + tap * 32 + ic;
            g_cw2h[o] = hh;
            g_cw2l[o] = ll;
        }
    } else if (bx < 9900) {
        int r = (bx - 9804) * 256 + t;
        out[r] = (r < NROW) ? b3a[0] : b3b[0];
    } else if (bx < 12972) {
        int i4 = (bx - 9900) * 256 + t;     // < 786432 float4s
        *(float4*)(g_act1 + (size_t)i4 * 4) = make_float4(0.f, 0.f, 0.f, 0.f);
    } else {
        if (t < 128) g_stats[t] = 0.f;
    }
}

// ====== persistent fused conv1(SIMT) + conv2(bf16x3 MMA), permuted-K out ======
#define CV_SMEM 57984
#define CV_SCAN 0          // 2 x 1024B double buffer
#define CV_W1   2048
#define CV_B1   2688
#define CV_B2   2816
#define CV_H1H  3072
#define CV_H1L  23872
#define CV_W2H  44672
#define CV_W2L  51328

__global__ void __launch_bounds__(256, 3) conv_kernel(
    const float* __restrict__ scan,
    const float* __restrict__ w1, const float* __restrict__ b1,
    const float* __restrict__ b2)
{
    extern __shared__ char smem[];
    const uint32_t sb = smem_u32(smem);
    float* s_w1   = (float*)(smem + CV_W1);
    float* s_b1   = (float*)(smem + CV_B1);
    float* s_b2   = (float*)(smem + CV_B2);
    __nv_bfloat16* s_h1h = (__nv_bfloat16*)(smem + CV_H1H);
    __nv_bfloat16* s_h1l = (__nv_bfloat16*)(smem + CV_H1L);

    const int t = threadIdx.x, lane = t & 31, wid = t >> 5;
    const int b = blockIdx.x;
    const int nrows = (b < 300) ? 28 : 27;
    const int start = b * 27 + min(b, 300);

    for (int i = t; i < 416; i += 256) {
        CPA16(sb + CV_W2H + i * 16, (const char*)g_cw2h + i * 16);
        CPA16(sb + CV_W2L + i * 16, (const char*)g_cw2l + i * 16);
    }
    if (t < 64)
        CPA16(sb + CV_SCAN + t * 16, (const char*)(scan + (size_t)start * 256) + t * 16);
    CPC();
    if (t < 160) s_w1[t] = w1[t];
    if (t < 32) { s_b1[t] = b1[t]; s_b2[t] = b2[t]; }
    asm volatile("cp.async.wait_group 0;" ::: "memory");
    __syncthreads();

    // conv1 mapping: thread owns ic-pair (t&15)*2 and 16 positions (t>>4)*16
    const int icp = (t & 15) * 2;
    const int pbase16 = (t >> 4) * 16;
    float wva[5], wvb[5];
    #pragma unroll
    for (int k = 0; k < 5; k++) {
        wva[k] = s_w1[icp * 5 + k];
        wvb[k] = s_w1[(icp + 1) * 5 + k];
    }
    const float c1ba = s_b1[icp];
    const float c1bb = s_b1[icp + 1];

    const int n0 = wid * 32;
    const int lr = lane & 15;
    const int kh = lane >> 4;
    const int browl = (lane & 7) + ((lane >> 4) << 3);
    const int bko = (lane >> 3) & 1;
    const float eb_lo0 = s_b2[(lane >> 2)];
    const float eb_hi0 = s_b2[(lane >> 2) + 8];
    const float eb_lo1 = s_b2[16 + (lane >> 2)];
    const float eb_hi1 = s_b2[16 + (lane >> 2) + 8];

    for (int i = 0; i < nrows; i++) {
        const int row = start + i;
        const float* sc = (const float*)(smem + CV_SCAN + (i & 1) * 1024);

        if (i + 1 < nrows && t < 64)
            CPA16(sb + CV_SCAN + ((i + 1) & 1) * 1024 + t * 16,
                  (const char*)(scan + (size_t)(row + 1) * 256) + t * 16);
        CPC();

        // conv1 (rolling window, paired-ic STS.32)
        {
            float win[5];
            #pragma unroll
            for (int k = 0; k < 4; k++) win[k] = sc[pbase16 + k];
            #pragma unroll
            for (int q = 0; q < 16; q++) {
                int p = pbase16 + q;
                win[4] = sc[(p + 4) & 255];
                float a0 = c1ba + wva[0] * win[0] + wva[1] * win[1] + wva[2] * win[2]
                                + wva[3] * win[3] + wva[4] * win[4];
                float a1 = c1bb + wvb[0] * win[0] + wvb[1] * win[1] + wvb[2] * win[2]
                                + wvb[3] * win[3] + wvb[4] * win[4];
                a0 = fmaxf(a0, 0.f);
                a1 = fmaxf(a1, 0.f);
                if (p >= 252) { a0 = 0.f; a1 = 0.f; }
                __nv_bfloat16 h0, l0, h1, l1;
                bsplit(a0, h0, l0);
                bsplit(a1, h1, l1);
                *(__nv_bfloat162*)(s_h1h + p * 40 + icp) = __halves2bfloat162(h0, h1);
                *(__nv_bfloat162*)(s_h1l + p * 40 + icp) = __halves2bfloat162(l0, l1);
                win[0] = win[1]; win[1] = win[2]; win[2] = win[3]; win[3] = win[4];
            }
        }
        if (t < 128) {
            int p = 256 + (t >> 5), icc = t & 31;
            s_h1h[p * 40 + icc] = __float2bfloat16(0.f);
            s_h1l[p * 40 + icc] = __float2bfloat16(0.f);
        }
        __syncthreads();

        float acc[2][4][4];
        #pragma unroll
        for (int a = 0; a < 2; a++)
            #pragma unroll
            for (int bq = 0; bq < 4; bq++)
                #pragma unroll
                for (int c = 0; c < 4; c++) acc[a][bq][c] = 0.f;

        #pragma unroll
        for (int ks = 0; ks < 6; ks++) {
            int tap = ks >> 1;
            int ic16 = (ks & 1) * 32;

            uint32_t awh[2][4], awl[2][4];
            #pragma unroll
            for (int mi = 0; mi < 2; mi++) {
                uint32_t a = sb + CV_W2H + (mi * 16 + lr) * 208 + ks * 32 + kh * 16;
                LDSM4(awh[mi][0], awh[mi][1], awh[mi][2], awh[mi][3], a);
                LDSM4(awl[mi][0], awl[mi][1], awl[mi][2], awl[mi][3], a + 6656);
            }
            uint32_t bh[2][4], bl[2][4];
            #pragma unroll
            for (int nt = 0; nt < 2; nt++) {
                int nrow = n0 + nt * 16 + browl + tap;
                uint32_t bb = sb + CV_H1H + nrow * 80 + ic16 + bko * 16;
                LDSM4(bh[nt][0], bh[nt][1], bh[nt][2], bh[nt][3], bb);
                LDSM4(bl[nt][0], bl[nt][1], bl[nt][2], bl[nt][3], bb + 20800);
            }
            #pragma unroll
            for (int mi = 0; mi < 2; mi++) {
                #pragma unroll
                for (int nj = 0; nj < 4; nj++) {
                    int nt = nj >> 1, hf = (nj & 1) * 2;
                    MMA16816(acc[mi][nj], awh[mi], &bh[nt][hf]);
                    MMA16816(acc[mi][nj], awh[mi], &bl[nt][hf]);
                    MMA16816(acc[mi][nj], awl[mi], &bh[nt][hf]);
                }
            }
        }

        __nv_bfloat16* oh = g_ah + (size_t)row * KPAD;
        __nv_bfloat16* ol = g_al + (size_t)row * KPAD;
        #pragma unroll
        for (int mi = 0; mi < 2; mi++) {
            float b_lo = mi ? eb_lo1 : eb_lo0;
            float b_hi = mi ? eb_hi1 : eb_hi0;
            #pragma unroll
            for (int c = 0; c < 2; c++) {
                uint32_t ph[4], pl[4];
                #pragma unroll
                for (int u = 0; u < 4; u++) {
                    int nj = c * 2 + (u >> 1);
                    int idx0 = (u & 1) * 2;
                    float bb = (u & 1) ? b_hi : b_lo;
                    float v0 = fmaxf(acc[mi][nj][idx0 + 0] + bb, 0.f);
                    float v1 = fmaxf(acc[mi][nj][idx0 + 1] + bb, 0.f);
                    __nv_bfloat16 h0, l0, h1, l1;
                    bsplit(v0, h0, l0);
                    bsplit(v1, h1, l1);
                    __nv_bfloat162 hh = __halves2bfloat162(h0, h1);
                    __nv_bfloat162 ll = __halves2bfloat162(l0, l1);
                    ph[u] = *(uint32_t*)&hh;
                    pl[u] = *(uint32_t*)&ll;
                }
                size_t off = (size_t)wid * 1024 + mi * 512 + c * 256 + lane * 8;
                *(uint4*)(oh + off) = make_uint4(ph[0], ph[1], ph[2], ph[3]);
                *(uint4*)(ol + off) = make_uint4(pl[0], pl[1], pl[2], pl[3]);
            }
        }

        asm volatile("cp.async.wait_group 0;" ::: "memory");
        __syncthreads();
    }
}

// -------- fc2 (256->10) + concat -> g_inps + stats accumulate --------
__global__ void __launch_bounds__(256) fc2_concat(
    const float* __restrict__ w2, const float* __restrict__ b2,
    const float* __restrict__ b1,
    const float* __restrict__ obs, const float* __restrict__ acts)
{
    __shared__ float fs[8][10];
    __shared__ float sh_s[64], sh_q[64];
    int warp = threadIdx.x >> 5, lane = threadIdx.x & 31;
    int r = blockIdx.x * 8 + warp;

    if (threadIdx.x < 64) { sh_s[threadIdx.x] = 0.f; sh_q[threadIdx.x] = 0.f; }
    __syncthreads();

    const float* p0 = g_act1 + (size_t)r * 256;
    float x[8];
    #pragma unroll
    for (int i = 0; i < 8; i++) {
        int c = lane + 32 * i;
        x[i] = fmaxf(p0[c] + b1[c], 0.f);
    }

    #pragma unroll
    for (int j = 0; j < 10; j++) {
        float s = 0.f;
        #pragma unroll
        for (int i = 0; i < 8; i++) s += x[i] * w2[j * 256 + lane + 32 * i];
        #pragma unroll
        for (int off = 16; off; off >>= 1) s += __shfl_xor_sync(0xffffffffu, s, off);
        if (lane == 0) fs[warp][j] = s + b2[j];
    }
    __syncwarp();

    float* ir = g_inps + (size_t)r * 60;
    for (int c = lane; c < 60; c += 32) {
        float v;
        if (c < 48)      v = obs[(size_t)r * 48 + c];
        else if (c < 50) v = acts[(size_t)r * 2 + (c - 48)];
        else             v = fs[warp][c - 50];
        ir[c] = v;
        atomicAdd(&sh_s[c], v);
        atomicAdd(&sh_q[c], v * v);
    }
    __syncthreads();
    if (threadIdx.x < 60) {
        atomicAdd(&g_stats[threadIdx.x], sh_s[threadIdx.x]);
        atomicAdd(&g_stats[64 + threadIdx.x], sh_q[threadIdx.x]);
    }
}

// -------- normalize (finalizing stats locally) + encoder(leaky) -> emb split ----
__global__ void __launch_bounds__(256) enc_kvq(
    const float* __restrict__ enc_w, const float* __restrict__ enc_b)
{
    __shared__ float xn[32][60];
    __shared__ float wch[32][61];
    __shared__ float mu_s[60], inv_s[60];

    int t = threadIdx.x;
    int row0 = blockIdx.x * 32;

    if (t < 60) {
        float mu = g_stats[t] * (1.f / NROW);
        float var = g_stats[64 + t] * (1.f / NROW) - mu * mu;
        mu_s[t] = mu;
        inv_s[t] = rsqrtf(var + 1e-5f);
    }
    __syncthreads();

    for (int idx = t; idx < 32 * 60; idx += 256) {
        int r = idx / 60, c = idx % 60;
        xn[r][c] = (g_inps[(size_t)(row0 + r) * 60 + c] - mu_s[c]) * inv_s[c];
    }
    __syncthreads();

    int jj = t & 31, rg = t >> 5;

    for (int jc = 0; jc < 4; jc++) {
        for (int idx = t; idx < 32 * 60; idx += 256) {
            int rr = idx / 60, c = idx % 60;
            wch[rr][c] = enc_w[(jc * 32 + rr) * 60 + c];
        }
        __syncthreads();

        float a0 = 0.f, a1 = 0.f, a2 = 0.f, a3 = 0.f;
        #pragma unroll
        for (int c = 0; c < 60; c++) {
            float w = wch[jj][c];
            a0 += xn[rg * 4 + 0][c] * w;
            a1 += xn[rg * 4 + 1][c] * w;
            a2 += xn[rg * 4 + 2][c] * w;
            a3 += xn[rg * 4 + 3][c] * w;
        }
        float bb = enc_b[jc * 32 + jj];
        float v[4] = {a0 + bb, a1 + bb, a2 + bb, a3 + bb};
        int col = jc * 32 + jj;
        #pragma unroll
        for (int q = 0; q < 4; q++) {
            float vv = (v[q] >= 0.f) ? v[q] : 0.01f * v[q];
            __nv_bfloat16 hh, ll;
            bsplit(vv, hh, ll);
            size_t idx = (size_t)(row0 + rg * 4 + q) * 256 + col;
            g_embh[idx] = hh;
            g_embl[idx] = ll;
        }
        __syncthreads();
    }
}

// ---------------- tiny 3-agent cross-attention ----------------
__global__ void __launch_bounds__(128) attn_kernel()
{
    __shared__ float qs[3][128], ks[3][128], vs[3][128];
    int b = blockIdx.x;
    int t = threadIdx.x;

    #pragma unroll
    for (int g = 0; g < 3; g++) {
        size_t roff = (size_t)(g * BSZ + b) * 128 + t;
        qs[g][t] = g_q[roff];
        ks[g][t] = g_keys[roff];
        vs[g][t] = g_vals[roff];
    }
    __syncthreads();

    const float scale = 0.25f;
    #pragma unroll
    for (int g = 0; g < 3; g++) {
        int o1 = (g == 0) ? 1 : 0;
        int o2 = (g == 2) ? 1 : 2;
        float q = qs[g][t];
        float p1 = q * ks[o1][t];
        float p2 = q * ks[o2][t];
        #pragma unroll
        for (int off = 8; off; off >>= 1) {
            p1 += __shfl_xor_sync(0xffffffffu, p1, off);
            p2 += __shfl_xor_sync(0xffffffffu, p2, off);
        }
        float l1 = p1 * scale, l2 = p2 * scale;
        float mx = fmaxf(l1, l2);
        float e1 = expf(l1 - mx), e2 = expf(l2 - mx);
        float inv = 1.f / (e1 + e2);
        float other = (e1 * vs[o1][t] + e2 * vs[o2][t]) * inv;
        __nv_bfloat16 hh, ll;
        bsplit(other, hh, ll);
        size_t idx = (size_t)(g * BSZ + b) * 256 + 128 + t;
        g_embh[idx] = hh;
        g_embl[idx] = ll;
    }
}

// ---------------- launch ----------------
extern "C" void kernel_launch(void* const* d_in, const int* in_sizes, int n_in,
                              void* d_out, int out_size)
{
    const float* obs     = (const float*)d_in[0];
    const float* acts    = (const float*)d_in[1];
    const float* scan    = (const float*)d_in[2];
    const float* conv_w1 = (const float*)d_in[3];
    const float* conv_b1 = (const float*)d_in[4];
    const float* conv_w2 = (const float*)d_in[5];
    const float* conv_b2 = (const float*)d_in[6];
    const float* fc_w1   = (const float*)d_in[7];
    const float* fc_b1   = (const float*)d_in[8];
    const float* fc_w2   = (const float*)d_in[9];
    const float* fc_b2   = (const float*)d_in[10];
    const float* enc_w   = (const float*)d_in[11];
    const float* enc_b   = (const float*)d_in[12];
    const float* Wk      = (const float*)d_in[13];
    const float* Wv      = (const float*)d_in[14];
    const float* bv      = (const float*)d_in[15];
    const float* Wq      = (const float*)d_in[16];
    const float* q1_w1   = (const float*)d_in[17];
    const float* q1_b1   = (const float*)d_in[18];
    const float* q1_w2   = (const float*)d_in[19];
    const float* q1_b2   = (const float*)d_in[20];
    const float* q1_w3   = (const float*)d_in[21];
    const float* q1_b3   = (const float*)d_in[22];
    const float* q2_w1   = (const float*)d_in[23];
    const float* q2_b1   = (const float*)d_in[24];
    const float* q2_w2   = (const float*)d_in[25];
    const float* q2_b2   = (const float*)d_in[26];
    const float* q2_w3   = (const float*)d_in[27];
    const float* q2_b3   = (const float*)d_in[28];
    float* out = (float*)d_out;

    cudaFuncSetAttribute(fc1_gemm, cudaFuncAttributeMaxDynamicSharedMemorySize, FSMEM);
    cudaFuncSetAttribute(mlp_gemm<1>, cudaFuncAttributeMaxDynamicSharedMemorySize, GSMEM1);
    cudaFuncSetAttribute(mlp_gemm<2>, cudaFuncAttributeMaxDynamicSharedMemorySize, GSMEM2);
    cudaFuncSetAttribute(kvq_gemm, cudaFuncAttributeMaxDynamicSharedMemorySize, GSMEM1);
    cudaFuncSetAttribute(conv_kernel, cudaFuncAttributeMaxDynamicSharedMemorySize, CV_SMEM);

    // all weight prep + out init (b3 bias) + act1 zero + stats zero in one launch
    wsplit_all<<<12973, 256>>>(fc_w1, q1_w1, q2_w1, q1_w2, q2_w2, conv_w2,
                               Wk, Wv, Wq, q1_b3, q2_b3, out);

    conv_kernel<<<444, 256, CV_SMEM>>>(scan, conv_w1, conv_b1, conv_b2);
    fc1_gemm<<<dim3(2, 96, 3), 256, FSMEM>>>();
    fc2_concat<<<NROW / 8, 256>>>(fc_w2, fc_b2, fc_b1, obs, acts);
    enc_kvq<<<NROW / 32, 256>>>(enc_w, enc_b);
    kvq_gemm<<<dim3(3, 64, 3), 256, GSMEM1>>>(bv);
    attn_kernel<<<BSZ, 128>>>();

    mlp_gemm<1><<<dim3(4, 192), 256, GSMEM1>>>(q1_b1, q2_b1, nullptr, nullptr, nullptr);
    mlp_gemm<2><<<dim3(2, 192, 2), 256, GSMEM2>>>(q1_b2, q2_b2, q1_w3, q2_w3, out);
}

// round 15
// speedup vs baseline: 1.0390x; 1.0390x over previous
#include <cuda_runtime.h>
#include <cuda_bf16.h>
#include <math.h>
#include <cstdint>

#define NROW 12288
#define BSZ  4096
#define KPAD 8192

// ---------------- scratch (device globals; no allocations) ----------------
__device__ __nv_bfloat16 g_ah[(size_t)NROW * KPAD];  // conv output hi (permuted K)
__device__ __nv_bfloat16 g_al[(size_t)NROW * KPAD];  // conv output lo
__device__ __nv_bfloat16 g_fwh[256 * KPAD];          // fc_w1 hi (same permutation)
__device__ __nv_bfloat16 g_fwl[256 * KPAD];          // fc_w1 lo
__device__ __nv_bfloat16 g_qwh[4 * 256 * 256];       // q1_w1,q2_w1,q1_w2,q2_w2 hi
__device__ __nv_bfloat16 g_qwl[4 * 256 * 256];       // lo
__device__ __nv_bfloat16 g_kvh[3 * 384 * 128];       // per-agent [Wk;Wv;Wq_g] hi
__device__ __nv_bfloat16 g_kvl[3 * 384 * 128];       // lo
__device__ __nv_bfloat16 g_cw2h[32 * 104];           // conv w2 pre-split (smem layout)
__device__ __nv_bfloat16 g_cw2l[32 * 104];
__device__ float g_part[3 * (size_t)NROW * 256];     // fc1 K-split partials
__device__ float g_inps[NROW * 60];
__device__ float g_stats[128];
__device__ __nv_bfloat16 g_embh[NROW * 256];
__device__ __nv_bfloat16 g_embl[NROW * 256];
__device__ __nv_bfloat16 g_mh[(size_t)NROW * 512];
__device__ __nv_bfloat16 g_ml[(size_t)NROW * 512];
__device__ float g_keys[NROW * 128];
__device__ float g_vals[NROW * 128];
__device__ float g_q[NROW * 128];

// ====================== helpers ======================
__device__ __forceinline__ uint32_t smem_u32(const void* p) {
    uint32_t a;
    asm("{ .reg .u64 t; cvta.to.shared.u64 t, %1; cvt.u32.u64 %0, t; }"
        : "=r"(a) : "l"(p));
    return a;
}
__device__ __forceinline__ void bsplit(float v, __nv_bfloat16& h, __nv_bfloat16& l) {
    h = __float2bfloat16(v);
    l = __float2bfloat16(v - __bfloat162float(h));
}
#define CPA16(s, g) \
    asm volatile("cp.async.cg.shared.global [%0], [%1], 16;" :: "r"(s), "l"(g))
#define CPC() asm volatile("cp.async.commit_group;" ::: "memory")
#define LDSM4(r0, r1, r2, r3, a) \
    asm volatile("ldmatrix.sync.aligned.m8n8.x4.shared.b16 {%0,%1,%2,%3}, [%4];" \
                 : "=r"(r0), "=r"(r1), "=r"(r2), "=r"(r3) : "r"(a))
#define MMA16816(d, a, b) \
    asm volatile("mma.sync.aligned.m16n8k16.row.col.f32.bf16.bf16.f32 " \
                 "{%0,%1,%2,%3},{%4,%5,%6,%7},{%8,%9},{%0,%1,%2,%3};" \
                 : "+f"((d)[0]), "+f"((d)[1]), "+f"((d)[2]), "+f"((d)[3]) \
                 : "r"((a)[0]), "r"((a)[1]), "r"((a)[2]), "r"((a)[3]), \
                   "r"((b)[0]), "r"((b)[1]))

// ================= fc1: bf16x3 GEMM, BM128/BN128/BK32, 3-stage, K-split =========
#define FSMEM (3 * 32768)
__global__ void __launch_bounds__(256, 2) fc1_gemm()
{
    extern __shared__ char smem[];
    const uint32_t sb = smem_u32(smem);

    const int t = threadIdx.x, lane = t & 31, wid = t >> 5;
    const int bn = blockIdx.x, bm = blockIdx.y, z = blockIdx.z;
    const int kt0 = (z == 0) ? 0 : (z == 1) ? 86 : 171;
    const int T   = (z == 0) ? 86 : 85;
    const int row0 = bm * 128, col0 = bn * 128;

    const int fr = t >> 1;
    const int c0 = (t & 1) * 2;
    const __nv_bfloat16* gAh = g_ah + (size_t)(row0 + fr) * KPAD + kt0 * 32;
    const __nv_bfloat16* gAl = g_al + (size_t)(row0 + fr) * KPAD + kt0 * 32;
    const __nv_bfloat16* gBh = g_fwh + (size_t)(col0 + fr) * KPAD + kt0 * 32;
    const __nv_bfloat16* gBl = g_fwl + (size_t)(col0 + fr) * KPAD + kt0 * 32;
    const int fsw = (fr >> 1) & 3;

    const int mw = wid & 1, nw = wid >> 1;

    float acc[4][4][4];
    #pragma unroll
    for (int a = 0; a < 4; a++)
        #pragma unroll
        for (int b = 0; b < 4; b++)
            #pragma unroll
            for (int c = 0; c < 4; c++) acc[a][b][c] = 0.f;

    auto fill = [&](int tt, int s) {
        uint32_t base = sb + s * 32768;
        const __nv_bfloat16* pAh = gAh + (size_t)tt * 32;
        const __nv_bfloat16* pAl = gAl + (size_t)tt * 32;
        const __nv_bfloat16* pBh = gBh + (size_t)tt * 32;
        const __nv_bfloat16* pBl = gBl + (size_t)tt * 32;
        #pragma unroll
        for (int j = 0; j < 2; j++) {
            int c = c0 + j;
            uint32_t off = fr * 64 + ((c ^ fsw) << 4);
            CPA16(base + off,         pAh + c * 8);
            CPA16(base + 8192 + off,  pAl + c * 8);
            CPA16(base + 16384 + off, pBh + c * 8);
            CPA16(base + 24576 + off, pBl + c * 8);
        }
    };

    fill(0, 0); CPC();
    fill(1, 1); CPC();

    for (int tt = 0; tt < T; tt++) {
        asm volatile("cp.async.wait_group 1;" ::: "memory");
        __syncthreads();

        const uint32_t stu = sb + (tt % 3) * 32768;
        #pragma unroll
        for (int ks = 0; ks < 2; ks++) {
            uint32_t bhf[2][4], blf[2][4];
            #pragma unroll
            for (int nt = 0; nt < 2; nt++) {
                int nr = nw * 32 + nt * 16 + (lane & 7) + ((lane >> 4) << 3);
                int cs = (ks * 2 + ((lane >> 3) & 1)) ^ ((nr >> 1) & 3);
                uint32_t ba = stu + 16384 + nr * 64 + cs * 16;
                LDSM4(bhf[nt][0], bhf[nt][1], bhf[nt][2], bhf[nt][3], ba);
                LDSM4(blf[nt][0], blf[nt][1], blf[nt][2], blf[nt][3], ba + 8192);
            }
            #pragma unroll
            for (int mi = 0; mi < 4; mi++) {
                int r = mw * 64 + mi * 16 + (lane & 15);
                int cs = (ks * 2 + (lane >> 4)) ^ ((r >> 1) & 3);
                uint32_t aa = stu + r * 64 + cs * 16;
                uint32_t ah[4], al[4];
                LDSM4(ah[0], ah[1], ah[2], ah[3], aa);
                LDSM4(al[0], al[1], al[2], al[3], aa + 8192);
                #pragma unroll
                for (int nj = 0; nj < 4; nj++) {
                    int nt = nj >> 1, hf = (nj & 1) * 2;
                    MMA16816(acc[mi][nj], ah, &bhf[nt][hf]);
                    MMA16816(acc[mi][nj], ah, &blf[nt][hf]);
                    MMA16816(acc[mi][nj], al, &bhf[nt][hf]);
                }
            }
        }

        if (tt + 2 < T) fill(tt + 2, (tt + 2) % 3);
        CPC();
    }

    float* P = g_part + (size_t)z * NROW * 256;
    #pragma unroll
    for (int mi = 0; mi < 4; mi++) {
        #pragma unroll
        for (int nj = 0; nj < 4; nj++) {
            int col = col0 + nw * 32 + nj * 8 + (lane & 3) * 2;
            #pragma unroll
            for (int h = 0; h < 2; h++) {
                int row = row0 + mw * 64 + mi * 16 + (lane >> 2) + h * 8;
                *(float2*)(P + (size_t)row * 256 + col) =
                    make_float2(acc[mi][nj][h * 2], acc[mi][nj][h * 2 + 1]);
            }
        }
    }
}

// ============ MLP GEMM: BM64/BN128/BK32, 3-stage, warp tile 32x32, bf16x3 ========
#define GSMEM1 (3 * 24576)
#define GSMEM2 (3 * 24576 + 1024)
template <int LAYER>
__global__ void __launch_bounds__(256, 2) mlp_gemm(
    const float* __restrict__ biasA, const float* __restrict__ biasB,
    const float* __restrict__ w3a, const float* __restrict__ w3b,
    float* __restrict__ out)
{
    const int z = (LAYER == 2) ? blockIdx.z : 0;
    const __nv_bfloat16* Ah = (LAYER == 1) ? g_embh : g_mh + z * 256;
    const __nv_bfloat16* Al = (LAYER == 1) ? g_embl : g_ml + z * 256;
    const int AS = (LAYER == 1) ? 256 : 512;
    const __nv_bfloat16* Bh = (LAYER == 1) ? g_qwh : g_qwh + (2 + z) * 65536;
    const __nv_bfloat16* Bl = (LAYER == 1) ? g_qwl : g_qwl + (2 + z) * 65536;

    extern __shared__ char smem[];
    const uint32_t sb = smem_u32(smem);
    float* w3s = (float*)(smem + 73728);

    const int t = threadIdx.x, lane = t & 31, wid = t >> 5;
    const int row0 = blockIdx.y * 64, col0 = blockIdx.x * 128;

    if (LAYER == 2) {
        if (t < 256) w3s[t] = (z ? w3b : w3a)[t];
    }

    const int ar = t >> 2, ac = t & 3;
    const int br = t >> 1, bc0 = (t & 1) * 2;
    const __nv_bfloat16* gAh = Ah + (size_t)(row0 + ar) * AS + ac * 8;
    const __nv_bfloat16* gAl = Al + (size_t)(row0 + ar) * AS + ac * 8;
    const __nv_bfloat16* gBh = Bh + (size_t)(col0 + br) * 256;
    const __nv_bfloat16* gBl = Bl + (size_t)(col0 + br) * 256;
    const uint32_t aoff = ar * 64 + ((ac ^ ((ar >> 1) & 3)) << 4);
    const int bsw = (br >> 1) & 3;

    const int mw = wid & 1, nw = wid >> 1;

    float acc[2][4][4];
    #pragma unroll
    for (int a = 0; a < 2; a++)
        #pragma unroll
        for (int b = 0; b < 4; b++)
            #pragma unroll
            for (int c = 0; c < 4; c++) acc[a][b][c] = 0.f;

    auto fill = [&](int tt, int s) {
        uint32_t base = sb + s * 24576;
        CPA16(base + aoff,        gAh + tt * 32);
        CPA16(base + 4096 + aoff, gAl + tt * 32);
        #pragma unroll
        for (int j = 0; j < 2; j++) {
            int c = bc0 + j;
            uint32_t boff = br * 64 + ((c ^ bsw) << 4);
            CPA16(base + 8192 + boff,  gBh + tt * 32 + c * 8);
            CPA16(base + 16384 + boff, gBl + tt * 32 + c * 8);
        }
    };

    fill(0, 0); CPC();
    fill(1, 1); CPC();

    const int T = 8;
    for (int tt = 0; tt < T; tt++) {
        asm volatile("cp.async.wait_group 1;" ::: "memory");
        __syncthreads();

        const uint32_t stu = sb + (tt % 3) * 24576;
        #pragma unroll
        for (int ks = 0; ks < 2; ks++) {
            uint32_t bhf[2][4], blf[2][4];
            #pragma unroll
            for (int nt = 0; nt < 2; nt++) {
                int nr = nw * 32 + nt * 16 + (lane & 7) + ((lane >> 4) << 3);
                int cs = (ks * 2 + ((lane >> 3) & 1)) ^ ((nr >> 1) & 3);
                uint32_t ba = stu + 8192 + nr * 64 + cs * 16;
                LDSM4(bhf[nt][0], bhf[nt][1], bhf[nt][2], bhf[nt][3], ba);
                LDSM4(blf[nt][0], blf[nt][1], blf[nt][2], blf[nt][3], ba + 8192);
            }
            #pragma unroll
            for (int mi = 0; mi < 2; mi++) {
                int r = mw * 32 + mi * 16 + (lane & 15);
                int cs = (ks * 2 + (lane >> 4)) ^ ((r >> 1) & 3);
                uint32_t aa = stu + r * 64 + cs * 16;
                uint32_t ah[4], al[4];
                LDSM4(ah[0], ah[1], ah[2], ah[3], aa);
                LDSM4(al[0], al[1], al[2], al[3], aa + 4096);
                #pragma unroll
                for (int nj = 0; nj < 4; nj++) {
                    int nt = nj >> 1, hf = (nj & 1) * 2;
                    MMA16816(acc[mi][nj], ah, &bhf[nt][hf]);
                    MMA16816(acc[mi][nj], ah, &blf[nt][hf]);
                    MMA16816(acc[mi][nj], al, &bhf[nt][hf]);
                }
            }
        }

        if (tt + 2 < T) fill(tt + 2, (tt + 2) % 3);
        CPC();
    }

    if (LAYER == 1) {
        #pragma unroll
        for (int mi = 0; mi < 2; mi++) {
            #pragma unroll
            for (int nj = 0; nj < 4; nj++) {
                int ocl = col0 + nw * 32 + nj * 8 + (lane & 3) * 2;
                float b0 = (ocl < 256) ? biasA[ocl] : biasB[ocl - 256];
                float b1 = (ocl + 1 < 256) ? biasA[ocl + 1] : biasB[ocl + 1 - 256];
                #pragma unroll
                for (int h = 0; h < 2; h++) {
                    int row = row0 + mw * 32 + mi * 16 + (lane >> 2) + h * 8;
                    float v0 = fmaxf(acc[mi][nj][h * 2 + 0] + b0, 0.f);
                    float v1 = fmaxf(acc[mi][nj][h * 2 + 1] + b1, 0.f);
                    size_t idx = (size_t)row * 512 + ocl;
                    __nv_bfloat16 h0, l0, h1, l1;
                    bsplit(v0, h0, l0);
                    bsplit(v1, h1, l1);
                    *(__nv_bfloat162*)(g_mh + idx) = __halves2bfloat162(h0, h1);
                    *(__nv_bfloat162*)(g_ml + idx) = __halves2bfloat162(l0, l1);
                }
            }
        }
    } else {
        const float* bb = z ? biasB : biasA;
        #pragma unroll
        for (int mi = 0; mi < 2; mi++) {
            #pragma unroll
            for (int h = 0; h < 2; h++) {
                int row = row0 + mw * 32 + mi * 16 + (lane >> 2) + h * 8;
                float s = 0.f;
                #pragma unroll
                for (int nj = 0; nj < 4; nj++) {
                    int ocl = col0 + nw * 32 + nj * 8 + (lane & 3) * 2;
                    float v0 = fmaxf(acc[mi][nj][h * 2 + 0] + bb[ocl], 0.f);
                    float v1 = fmaxf(acc[mi][nj][h * 2 + 1] + bb[ocl + 1], 0.f);
                    s += v0 * w3s[ocl] + v1 * w3s[ocl + 1];
                }
                s += __shfl_xor_sync(0xffffffffu, s, 1);
                s += __shfl_xor_sync(0xffffffffu, s, 2);
                if ((lane & 3) == 0) atomicAdd(&out[z * NROW + row], s);
            }
        }
    }
}

// ========= kvq_gemm: keys/vals/q via bf16x3, BM64/BN128/BK32, K=128 =========
__global__ void __launch_bounds__(256, 2) kvq_gemm(const float* __restrict__ bv)
{
    const int m = blockIdx.x;
    const int g = blockIdx.z;
    const int row0 = g * 4096 + blockIdx.y * 64;
    const int col0 = m * 128;

    extern __shared__ char smem[];
    const uint32_t sb = smem_u32(smem);

    const int t = threadIdx.x, lane = t & 31, wid = t >> 5;

    const int ar = t >> 2, ac = t & 3;
    const int br = t >> 1, bc0 = (t & 1) * 2;
    const __nv_bfloat16* gAh = g_embh + (size_t)(row0 + ar) * 256 + ac * 8;
    const __nv_bfloat16* gAl = g_embl + (size_t)(row0 + ar) * 256 + ac * 8;
    const __nv_bfloat16* gBh = g_kvh + (size_t)g * 49152 + (size_t)(col0 + br) * 128;
    const __nv_bfloat16* gBl = g_kvl + (size_t)g * 49152 + (size_t)(col0 + br) * 128;
    const uint32_t aoff = ar * 64 + ((ac ^ ((ar >> 1) & 3)) << 4);
    const int bsw = (br >> 1) & 3;

    const int mw = wid & 1, nw = wid >> 1;

    float acc[2][4][4];
    #pragma unroll
    for (int a = 0; a < 2; a++)
        #pragma unroll
        for (int b = 0; b < 4; b++)
            #pragma unroll
            for (int c = 0; c < 4; c++) acc[a][b][c] = 0.f;

    auto fill = [&](int tt, int s) {
        uint32_t base = sb + s * 24576;
        CPA16(base + aoff,        gAh + tt * 32);
        CPA16(base + 4096 + aoff, gAl + tt * 32);
        #pragma unroll
        for (int j = 0; j < 2; j++) {
            int c = bc0 + j;
            uint32_t boff = br * 64 + ((c ^ bsw) << 4);
            CPA16(base + 8192 + boff,  gBh + tt * 32 + c * 8);
            CPA16(base + 16384 + boff, gBl + tt * 32 + c * 8);
        }
    };

    fill(0, 0); CPC();
    fill(1, 1); CPC();

    const int T = 4;
    for (int tt = 0; tt < T; tt++) {
        if (tt == T - 1)
            asm volatile("cp.async.wait_group 0;" ::: "memory");
        else
            asm volatile("cp.async.wait_group 1;" ::: "memory");
        __syncthreads();

        const uint32_t stu = sb + (tt % 3) * 24576;
        #pragma unroll
        for (int ks = 0; ks < 2; ks++) {
            uint32_t bhf[2][4], blf[2][4];
            #pragma unroll
            for (int nt = 0; nt < 2; nt++) {
                int nr = nw * 32 + nt * 16 + (lane & 7) + ((lane >> 4) << 3);
                int cs = (ks * 2 + ((lane >> 3) & 1)) ^ ((nr >> 1) & 3);
                uint32_t ba = stu + 8192 + nr * 64 + cs * 16;
                LDSM4(bhf[nt][0], bhf[nt][1], bhf[nt][2], bhf[nt][3], ba);
                LDSM4(blf[nt][0], blf[nt][1], blf[nt][2], blf[nt][3], ba + 8192);
            }
            #pragma unroll
            for (int mi = 0; mi < 2; mi++) {
                int r = mw * 32 + mi * 16 + (lane & 15);
                int cs = (ks * 2 + (lane >> 4)) ^ ((r >> 1) & 3);
                uint32_t aa = stu + r * 64 + cs * 16;
                uint32_t ah[4], al[4];
                LDSM4(ah[0], ah[1], ah[2], ah[3], aa);
                LDSM4(al[0], al[1], al[2], al[3], aa + 4096);
                #pragma unroll
                for (int nj = 0; nj < 4; nj++) {
                    int nt = nj >> 1, hf = (nj & 1) * 2;
                    MMA16816(acc[mi][nj], ah, &bhf[nt][hf]);
                    MMA16816(acc[mi][nj], ah, &blf[nt][hf]);
                    MMA16816(acc[mi][nj], al, &bhf[nt][hf]);
                }
            }
        }

        if (tt + 2 < T) fill(tt + 2, (tt + 2) % 3);
        CPC();
    }

    float* Out = (m == 0) ? g_keys : (m == 1) ? g_vals : g_q;
    #pragma unroll
    for (int mi = 0; mi < 2; mi++) {
        #pragma unroll
        for (int nj = 0; nj < 4; nj++) {
            int col = nw * 32 + nj * 8 + (lane & 3) * 2;
            float b0 = 0.f, b1 = 0.f;
            if (m == 1) { b0 = bv[col]; b1 = bv[col + 1]; }
            #pragma unroll
            for (int h = 0; h < 2; h++) {
                int row = row0 + mw * 32 + mi * 16 + (lane >> 2) + h * 8;
                float v0 = acc[mi][nj][h * 2 + 0] + b0;
                float v1 = acc[mi][nj][h * 2 + 1] + b1;
                if (m == 1) {
                    v0 = (v0 >= 0.f) ? v0 : 0.01f * v0;
                    v1 = (v1 >= 0.f) ? v1 : 0.01f * v1;
                }
                *(float2*)(Out + (size_t)row * 128 + col) = make_float2(v0, v1);
            }
        }
    }
}

// ---------------- combined weight prep / init kernel ----------------
__global__ void wsplit_all(
    const float* __restrict__ fw,
    const float* __restrict__ qa, const float* __restrict__ qb,
    const float* __restrict__ qc, const float* __restrict__ qd,
    const float* __restrict__ cw2,
    const float* __restrict__ Wk, const float* __restrict__ Wv,
    const float* __restrict__ Wq,
    const float* __restrict__ b3a, const float* __restrict__ b3b,
    float* __restrict__ out)
{
    __shared__ float sw[32][33];
    const int bx = blockIdx.x, t = threadIdx.x;
    if (bx < 2048) {
        // fc_w1 permuted split, smem-staged: block = (r, wq)
        const int r = bx >> 3, wq = bx & 7;
        for (int i = t; i < 1024; i += 256) {
            int oc = i >> 5, j = i & 31;
            int pos = wq * 32 + j;
            sw[oc][j] = (pos < 250) ? fw[r * 8000 + oc * 250 + pos] : 0.f;
        }
        __syncthreads();
        size_t base = (size_t)r * KPAD + wq * 1024;
        for (int i = t; i < 1024; i += 256) {
            int rem = i;
            int mi = rem >> 9;
            int c  = (rem >> 8) & 1;
            int l  = (rem >> 3) & 31;
            int e  = rem & 7;
            int idx = e & 3;
            int nj  = c * 2 + (e >> 2);
            int oc  = mi * 16 + (l >> 2) + (idx >> 1) * 8;
            int j   = nj * 8 + (l & 3) * 2 + (e & 1);
            __nv_bfloat16 hh, ll;
            bsplit(sw[oc][j], hh, ll);
            g_fwh[base + rem] = hh;
            g_fwl[base + rem] = ll;
        }
    } else if (bx < 3072) {
        int i = (bx - 2048) * 256 + t;
        int which = i >> 16, j = i & 65535;
        const float* src = (which == 0) ? qa : (which == 1) ? qb : (which == 2) ? qc : qd;
        __nv_bfloat16 hh, ll;
        bsplit(src[j], hh, ll);
        g_qwh[i] = hh;
        g_qwl[i] = ll;
    } else if (bx < 3648) {
        int j = (bx - 3072) * 256 + t;      // < 147456
        int g = j / 49152, rem = j % 49152;
        int rowj = rem >> 7, k = rem & 127;
        float v = (rowj < 128) ? Wk[rowj * 128 + k]
                : (rowj < 256) ? Wv[(rowj - 128) * 128 + k]
                : Wq[g * 16384 + (rowj - 256) * 128 + k];
        __nv_bfloat16 hh, ll;
        bsplit(v, hh, ll);
        g_kvh[j] = hh;
        g_kvl[j] = ll;
    } else if (bx < 3660) {
        int idx = (bx - 3648) * 256 + t;
        if (idx < 3072) {
            int oc = idx / 96, rem = idx % 96;
            int ic = rem / 3, tap = rem % 3;
            __nv_bfloat16 hh, ll;
            bsplit(cw2[idx], hh, ll);
            int o = oc * 104 + tap * 32 + ic;
            g_cw2h[o] = hh;
            g_cw2l[o] = ll;
        }
    } else if (bx < 3756) {
        int r = (bx - 3660) * 256 + t;      // < 24576
        out[r] = (r < NROW) ? b3a[0] : b3b[0];
    } else {
        if (t < 128) g_stats[t] = 0.f;
    }
}

// ====== persistent fused conv1(SIMT) + conv2(bf16x3 MMA), permuted-K out ======
#define CV_SMEM 57984
#define CV_SCAN 0          // 2 x 1024B double buffer
#define CV_W1   2048
#define CV_B1   2688
#define CV_B2   2816
#define CV_H1H  3072
#define CV_H1L  23872
#define CV_W2H  44672
#define CV_W2L  51328

__global__ void __launch_bounds__(256, 3) conv_kernel(
    const float* __restrict__ scan,
    const float* __restrict__ w1, const float* __restrict__ b1,
    const float* __restrict__ b2)
{
    extern __shared__ char smem[];
    const uint32_t sb = smem_u32(smem);
    float* s_w1   = (float*)(smem + CV_W1);
    float* s_b1   = (float*)(smem + CV_B1);
    float* s_b2   = (float*)(smem + CV_B2);
    __nv_bfloat16* s_h1h = (__nv_bfloat16*)(smem + CV_H1H);
    __nv_bfloat16* s_h1l = (__nv_bfloat16*)(smem + CV_H1L);

    const int t = threadIdx.x, lane = t & 31, wid = t >> 5;
    const int b = blockIdx.x;
    const int nrows = (b < 300) ? 28 : 27;
    const int start = b * 27 + min(b, 300);

    for (int i = t; i < 416; i += 256) {
        CPA16(sb + CV_W2H + i * 16, (const char*)g_cw2h + i * 16);
        CPA16(sb + CV_W2L + i * 16, (const char*)g_cw2l + i * 16);
    }
    if (t < 64)
        CPA16(sb + CV_SCAN + t * 16, (const char*)(scan + (size_t)start * 256) + t * 16);
    CPC();
    if (t < 160) s_w1[t] = w1[t];
    if (t < 32) { s_b1[t] = b1[t]; s_b2[t] = b2[t]; }
    asm volatile("cp.async.wait_group 0;" ::: "memory");
    __syncthreads();

    const int ic = lane;
    const int pbase = wid * 32;
    float wv[5];
    #pragma unroll
    for (int k = 0; k < 5; k++) wv[k] = s_w1[ic * 5 + k];
    const float c1b = s_b1[ic];

    const int n0 = wid * 32;
    const int lr = lane & 15;
    const int kh = lane >> 4;
    const int browl = (lane & 7) + ((lane >> 4) << 3);
    const int bko = (lane >> 3) & 1;
    const float eb_lo0 = s_b2[(lane >> 2)];
    const float eb_hi0 = s_b2[(lane >> 2) + 8];
    const float eb_lo1 = s_b2[16 + (lane >> 2)];
    const float eb_hi1 = s_b2[16 + (lane >> 2) + 8];

    for (int i = 0; i < nrows; i++) {
        const int row = start + i;
        const float* sc = (const float*)(smem + CV_SCAN + (i & 1) * 1024);

        if (i + 1 < nrows && t < 64)
            CPA16(sb + CV_SCAN + ((i + 1) & 1) * 1024 + t * 16,
                  (const char*)(scan + (size_t)(row + 1) * 256) + t * 16);
        CPC();

        {
            float win[5];
            #pragma unroll
            for (int k = 0; k < 4; k++) win[k] = sc[pbase + k];
            #pragma unroll
            for (int q = 0; q < 32; q++) {
                int p = pbase + q;
                win[4] = sc[(p + 4) & 255];
                float a = c1b + wv[0] * win[0] + wv[1] * win[1] + wv[2] * win[2]
                              + wv[3] * win[3] + wv[4] * win[4];
                a = fmaxf(a, 0.f);
                if (p >= 252) a = 0.f;
                __nv_bfloat16 hh, ll;
                bsplit(a, hh, ll);
                s_h1h[p * 40 + ic] = hh;
                s_h1l[p * 40 + ic] = ll;
                win[0] = win[1]; win[1] = win[2]; win[2] = win[3]; win[3] = win[4];
            }
        }
        if (t < 128) {
            int p = 256 + (t >> 5), icc = t & 31;
            s_h1h[p * 40 + icc] = __float2bfloat16(0.f);
            s_h1l[p * 40 + icc] = __float2bfloat16(0.f);
        }
        __syncthreads();

        float acc[2][4][4];
        #pragma unroll
        for (int a = 0; a < 2; a++)
            #pragma unroll
            for (int bq = 0; bq < 4; bq++)
                #pragma unroll
                for (int c = 0; c < 4; c++) acc[a][bq][c] = 0.f;

        #pragma unroll
        for (int ks = 0; ks < 6; ks++) {
            int tap = ks >> 1;
            int ic16 = (ks & 1) * 32;

            uint32_t awh[2][4], awl[2][4];
            #pragma unroll
            for (int mi = 0; mi < 2; mi++) {
                uint32_t a = sb + CV_W2H + (mi * 16 + lr) * 208 + ks * 32 + kh * 16;
                LDSM4(awh[mi][0], awh[mi][1], awh[mi][2], awh[mi][3], a);
                LDSM4(awl[mi][0], awl[mi][1], awl[mi][2], awl[mi][3], a + 6656);
            }
            uint32_t bh[2][4], bl[2][4];
            #pragma unroll
            for (int nt = 0; nt < 2; nt++) {
                int nrow = n0 + nt * 16 + browl + tap;
                uint32_t bb = sb + CV_H1H + nrow * 80 + ic16 + bko * 16;
                LDSM4(bh[nt][0], bh[nt][1], bh[nt][2], bh[nt][3], bb);
                LDSM4(bl[nt][0], bl[nt][1], bl[nt][2], bl[nt][3], bb + 20800);
            }
            #pragma unroll
            for (int mi = 0; mi < 2; mi++) {
                #pragma unroll
                for (int nj = 0; nj < 4; nj++) {
                    int nt = nj >> 1, hf = (nj & 1) * 2;
                    MMA16816(acc[mi][nj], awh[mi], &bh[nt][hf]);
                    MMA16816(acc[mi][nj], awh[mi], &bl[nt][hf]);
                    MMA16816(acc[mi][nj], awl[mi], &bh[nt][hf]);
                }
            }
        }

        __nv_bfloat16* oh = g_ah + (size_t)row * KPAD;
        __nv_bfloat16* ol = g_al + (size_t)row * KPAD;
        #pragma unroll
        for (int mi = 0; mi < 2; mi++) {
            float b_lo = mi ? eb_lo1 : eb_lo0;
            float b_hi = mi ? eb_hi1 : eb_hi0;
            #pragma unroll
            for (int c = 0; c < 2; c++) {
                uint32_t ph[4], pl[4];
                #pragma unroll
                for (int u = 0; u < 4; u++) {
                    int nj = c * 2 + (u >> 1);
                    int idx0 = (u & 1) * 2;
                    float bb = (u & 1) ? b_hi : b_lo;
                    float v0 = fmaxf(acc[mi][nj][idx0 + 0] + bb, 0.f);
                    float v1 = fmaxf(acc[mi][nj][idx0 + 1] + bb, 0.f);
                    __nv_bfloat16 h0, l0, h1, l1;
                    bsplit(v0, h0, l0);
                    bsplit(v1, h1, l1);
                    __nv_bfloat162 hh = __halves2bfloat162(h0, h1);
                    __nv_bfloat162 ll = __halves2bfloat162(l0, l1);
                    ph[u] = *(uint32_t*)&hh;
                    pl[u] = *(uint32_t*)&ll;
                }
                size_t off = (size_t)wid * 1024 + mi * 512 + c * 256 + lane * 8;
                *(uint4*)(oh + off) = make_uint4(ph[0], ph[1], ph[2], ph[3]);
                *(uint4*)(ol + off) = make_uint4(pl[0], pl[1], pl[2], pl[3]);
            }
        }

        asm volatile("cp.async.wait_group 0;" ::: "memory");
        __syncthreads();
    }
}

// -------- fc1 combine + fc2 (256->10) + concat -> g_inps + stats (float4) --------
__global__ void __launch_bounds__(256) fc2_concat(
    const float* __restrict__ w2, const float* __restrict__ b2,
    const float* __restrict__ b1,
    const float* __restrict__ obs, const float* __restrict__ acts)
{
    __shared__ float fs[8][10];
    __shared__ float sh_s[64], sh_q[64];
    int warp = threadIdx.x >> 5, lane = threadIdx.x & 31;
    int r = blockIdx.x * 8 + warp;

    if (threadIdx.x < 64) { sh_s[threadIdx.x] = 0.f; sh_q[threadIdx.x] = 0.f; }
    __syncthreads();

    const float4* p0 = (const float4*)(g_part + (size_t)r * 256);
    const float4* p1 = p0 + (size_t)NROW * 64;
    const float4* p2 = p1 + (size_t)NROW * 64;
    const float4* b14 = (const float4*)b1;
    float4 x4[2];
    #pragma unroll
    for (int i = 0; i < 2; i++) {
        int c4 = lane + 32 * i;
        float4 a = p0[c4], bq = p1[c4], cq = p2[c4], bb = b14[c4];
        x4[i].x = fmaxf(a.x + bq.x + cq.x + bb.x, 0.f);
        x4[i].y = fmaxf(a.y + bq.y + cq.y + bb.y, 0.f);
        x4[i].z = fmaxf(a.z + bq.z + cq.z + bb.z, 0.f);
        x4[i].w = fmaxf(a.w + bq.w + cq.w + bb.w, 0.f);
    }

    #pragma unroll
    for (int j = 0; j < 10; j++) {
        const float4* w4 = (const float4*)(w2 + j * 256);
        float4 wa = w4[lane], wb = w4[lane + 32];
        float s = x4[0].x * wa.x + x4[0].y * wa.y + x4[0].z * wa.z + x4[0].w * wa.w
                + x4[1].x * wb.x + x4[1].y * wb.y + x4[1].z * wb.z + x4[1].w * wb.w;
        #pragma unroll
        for (int off = 16; off; off >>= 1) s += __shfl_xor_sync(0xffffffffu, s, off);
        if (lane == 0) fs[warp][j] = s + b2[j];
    }
    __syncwarp();

    float* ir = g_inps + (size_t)r * 60;
    for (int c = lane; c < 60; c += 32) {
        float v;
        if (c < 48)      v = obs[(size_t)r * 48 + c];
        else if (c < 50) v = acts[(size_t)r * 2 + (c - 48)];
        else             v = fs[warp][c - 50];
        ir[c] = v;
        atomicAdd(&sh_s[c], v);
        atomicAdd(&sh_q[c], v * v);
    }
    __syncthreads();
    if (threadIdx.x < 60) {
        atomicAdd(&g_stats[threadIdx.x], sh_s[threadIdx.x]);
        atomicAdd(&g_stats[64 + threadIdx.x], sh_q[threadIdx.x]);
    }
}

// -------- normalize (finalizing stats locally) + encoder(leaky) -> emb split ----
__global__ void __launch_bounds__(256) enc_kvq(
    const float* __restrict__ enc_w, const float* __restrict__ enc_b)
{
    __shared__ float xn[32][60];
    __shared__ float wch[32][61];
    __shared__ float mu_s[60], inv_s[60];

    int t = threadIdx.x;
    int row0 = blockIdx.x * 32;

    if (t < 60) {
        float mu = g_stats[t] * (1.f / NROW);
        float var = g_stats[64 + t] * (1.f / NROW) - mu * mu;
        mu_s[t] = mu;
        inv_s[t] = rsqrtf(var + 1e-5f);
    }
    __syncthreads();

    for (int idx = t; idx < 32 * 60; idx += 256) {
        int r = idx / 60, c = idx % 60;
        xn[r][c] = (g_inps[(size_t)(row0 + r) * 60 + c] - mu_s[c]) * inv_s[c];
    }
    __syncthreads();

    int jj = t & 31, rg = t >> 5;

    for (int jc = 0; jc < 4; jc++) {
        for (int idx = t; idx < 32 * 60; idx += 256) {
            int rr = idx / 60, c = idx % 60;
            wch[rr][c] = enc_w[(jc * 32 + rr) * 60 + c];
        }
        __syncthreads();

        float a0 = 0.f, a1 = 0.f, a2 = 0.f, a3 = 0.f;
        #pragma unroll
        for (int c = 0; c < 60; c++) {
            float w = wch[jj][c];
            a0 += xn[rg * 4 + 0][c] * w;
            a1 += xn[rg * 4 + 1][c] * w;
            a2 += xn[rg * 4 + 2][c] * w;
            a3 += xn[rg * 4 + 3][c] * w;
        }
        float bb = enc_b[jc * 32 + jj];
        float v[4] = {a0 + bb, a1 + bb, a2 + bb, a3 + bb};
        int col = jc * 32 + jj;
        #pragma unroll
        for (int q = 0; q < 4; q++) {
            float vv = (v[q] >= 0.f) ? v[q] : 0.01f * v[q];
            __nv_bfloat16 hh, ll;
            bsplit(vv, hh, ll);
            size_t idx = (size_t)(row0 + rg * 4 + q) * 256 + col;
            g_embh[idx] = hh;
            g_embl[idx] = ll;
        }
        __syncthreads();
    }
}

// ---------------- tiny 3-agent cross-attention (2 batches/block) ----------------
__global__ void __launch_bounds__(256) attn_kernel()
{
    __shared__ float qs[2][3][128], ks[2][3][128], vs[2][3][128];
    int half = threadIdx.x >> 7, t = threadIdx.x & 127;
    int b = blockIdx.x * 2 + half;

    #pragma unroll
    for (int g = 0; g < 3; g++) {
        size_t roff = (size_t)(g * BSZ + b) * 128 + t;
        qs[half][g][t] = g_q[roff];
        ks[half][g][t] = g_keys[roff];
        vs[half][g][t] = g_vals[roff];
    }
    __syncwarp();

    const float scale = 0.25f;
    #pragma unroll
    for (int g = 0; g < 3; g++) {
        int o1 = (g == 0) ? 1 : 0;
        int o2 = (g == 2) ? 1 : 2;
        float q = qs[half][g][t];
        float p1 = q * ks[half][o1][t];
        float p2 = q * ks[half][o2][t];
        #pragma unroll
        for (int off = 8; off; off >>= 1) {
            p1 += __shfl_xor_sync(0xffffffffu, p1, off);
            p2 += __shfl_xor_sync(0xffffffffu, p2, off);
        }
        float l1 = p1 * scale, l2 = p2 * scale;
        float mx = fmaxf(l1, l2);
        float e1 = expf(l1 - mx), e2 = expf(l2 - mx);
        float inv = 1.f / (e1 + e2);
        float other = (e1 * vs[half][o1][t] + e2 * vs[half][o2][t]) * inv;
        __nv_bfloat16 hh, ll;
        bsplit(other, hh, ll);
        size_t idx = (size_t)(g * BSZ + b) * 256 + 128 + t;
        g_embh[idx] = hh;
        g_embl[idx] = ll;
    }
}

// ---------------- launch ----------------
extern "C" void kernel_launch(void* const* d_in, const int* in_sizes, int n_in,
                              void* d_out, int out_size)
{
    const float* obs     = (const float*)d_in[0];
    const float* acts    = (const float*)d_in[1];
    const float* scan    = (const float*)d_in[2];
    const float* conv_w1 = (const float*)d_in[3];
    const float* conv_b1 = (const float*)d_in[4];
    const float* conv_w2 = (const float*)d_in[5];
    const float* conv_b2 = (const float*)d_in[6];
    const float* fc_w1   = (const float*)d_in[7];
    const float* fc_b1   = (const float*)d_in[8];
    const float* fc_w2   = (const float*)d_in[9];
    const float* fc_b2   = (const float*)d_in[10];
    const float* enc_w   = (const float*)d_in[11];
    const float* enc_b   = (const float*)d_in[12];
    const float* Wk      = (const float*)d_in[13];
    const float* Wv      = (const float*)d_in[14];
    const float* bv      = (const float*)d_in[15];
    const float* Wq      = (const float*)d_in[16];
    const float* q1_w1   = (const float*)d_in[17];
    const float* q1_b1   = (const float*)d_in[18];
    const float* q1_w2   = (const float*)d_in[19];
    const float* q1_b2   = (const float*)d_in[20];
    const float* q1_w3   = (const float*)d_in[21];
    const float* q1_b3   = (const float*)d_in[22];
    const float* q2_w1   = (const float*)d_in[23];
    const float* q2_b1   = (const float*)d_in[24];
    const float* q2_w2   = (const float*)d_in[25];
    const float* q2_b2   = (const float*)d_in[26];
    const float* q2_w3   = (const float*)d_in[27];
    const float* q2_b3   = (const float*)d_in[28];
    float* out = (float*)d_out;

    cudaFuncSetAttribute(fc1_gemm, cudaFuncAttributeMaxDynamicSharedMemorySize, FSMEM);
    cudaFuncSetAttribute(mlp_gemm<1>, cudaFuncAttributeMaxDynamicSharedMemorySize, GSMEM1);
    cudaFuncSetAttribute(mlp_gemm<2>, cudaFuncAttributeMaxDynamicSharedMemorySize, GSMEM2);
    cudaFuncSetAttribute(kvq_gemm, cudaFuncAttributeMaxDynamicSharedMemorySize, GSMEM1);
    cudaFuncSetAttribute(conv_kernel, cudaFuncAttributeMaxDynamicSharedMemorySize, CV_SMEM);

    // all weight prep + out init (b3 bias) + stats zero in one launch
    wsplit_all<<<3757, 256>>>(fc_w1, q1_w1, q2_w1, q1_w2, q2_w2, conv_w2,
                              Wk, Wv, Wq, q1_b3, q2_b3, out);

    conv_kernel<<<444, 256, CV_SMEM>>>(scan, conv_w1, conv_b1, conv_b2);
    fc1_gemm<<<dim3(2, 96, 3), 256, FSMEM>>>();
    fc2_concat<<<NROW / 8, 256>>>(fc_w2, fc_b2, fc_b1, obs, acts);
    enc_kvq<<<NROW / 32, 256>>>(enc_w, enc_b);
    kvq_gemm<<<dim3(3, 64, 3), 256, GSMEM1>>>(bv);
    attn_kernel<<<2048, 256>>>();

    mlp_gemm<1><<<dim3(4, 192), 256, GSMEM1>>>(q1_b1, q2_b1, nullptr, nullptr, nullptr);
    mlp_gemm<2><<<dim3(2, 192, 2), 256, GSMEM2>>>(q1_b2, q2_b2, q1_w3, q2_w3, out);
}